// round 2
// baseline (speedup 1.0000x reference)
#include <cuda_runtime.h>
#include <cstddef>

// HBV hydrological model, fused time-scan kernel.
// x:          (NSTEP, NGRID, 3)  float32   [P, T, PET]
// parameters: (NSTEP, NGRID, 12, 1) float32 — ONLY the last timestep is used
// out:        concat(flow, AET, SWE), each (NSTEP, NGRID, 1) float32
//
// One thread per grid cell; sequential recurrence over 730 steps.
// Latency-bound: 313 warps total. 128-thread blocks -> 1 warp per SMSP.
// Depth-10 double-buffered register prefetch of x hides DRAM latency.

#define NSTEP 730
#define NGRID 10000
#define PFD   10   // prefetch depth; NSTEP % PFD == 0

__global__ __launch_bounds__(128, 1)
void hbv_kernel(const float* __restrict__ x,
                const float* __restrict__ params,
                float* __restrict__ out)
{
    const int cell = blockIdx.x * blockDim.x + threadIdx.x;
    if (cell >= NGRID) return;

    // --- per-cell parameters (last timestep only) ---
    const float* p = params + ((size_t)(NSTEP - 1) * NGRID + (size_t)cell) * 12;
    const float BETA    = 1.0f   + p[0]  * 5.0f;
    const float FC      = 50.0f  + p[1]  * 950.0f;
    const float K0      = 0.05f  + p[2]  * 0.85f;
    const float K1      = 0.01f  + p[3]  * 0.49f;
    const float K2      = 0.001f + p[4]  * 0.199f;
    const float LP      = 0.2f   + p[5]  * 0.8f;
    const float PERCmax =          p[6]  * 10.0f;
    const float UZL     =          p[7]  * 100.0f;
    const float TT      = -2.5f  + p[8]  * 5.0f;
    const float CFMAX   = 0.5f   + p[9]  * 9.5f;
    const float CFR     =          p[10] * 0.1f;
    const float CWH     =          p[11] * 0.2f;

    // hoisted invariants (remove in-loop divisions)
    const float invFC    = 1.0f / FC;
    const float invLPFC  = 1.0f / (LP * FC);
    const float CFRCFMAX = CFR * CFMAX;

    // --- state ---
    float SNOWPACK = 0.001f, MELTWATER = 0.001f, SM = 0.001f;
    float SUZ = 0.001f, SLZ = 0.001f;

    const size_t n = (size_t)NSTEP * NGRID;
    float* __restrict__ q_out = out;
    float* __restrict__ a_out = out + n;
    float* __restrict__ s_out = out + 2 * n;

    // --- prefetch buffers ---
    float bP[PFD], bT[PFD], bE[PFD];
#pragma unroll
    for (int j = 0; j < PFD; ++j) {
        const float* xp = x + ((size_t)j * NGRID + (size_t)cell) * 3;
        bP[j] = xp[0]; bT[j] = xp[1]; bE[j] = xp[2];
    }

    size_t oidx = (size_t)cell;

    for (int t0 = 0; t0 < NSTEP; t0 += PFD) {
        // issue next chunk's loads (MLP = 3*PFD) before computing this chunk
        float nP[PFD], nT[PFD], nE[PFD];
        {
            int tb = t0 + PFD;
            if (tb >= NSTEP) tb = NSTEP - PFD;   // clamped dummy prefetch on last chunk
#pragma unroll
            for (int j = 0; j < PFD; ++j) {
                const float* xp = x + ((size_t)(tb + j) * NGRID + (size_t)cell) * 3;
                nP[j] = xp[0]; nT[j] = xp[1]; nE[j] = xp[2];
            }
        }

#pragma unroll
        for (int j = 0; j < PFD; ++j) {
            const float Pt = bP[j], Tt = bT[j], PETt = bE[j];

            // snow partition
            const float RAIN = (Tt >= TT) ? Pt : 0.0f;
            const float SNOW = Pt - RAIN;
            SNOWPACK += SNOW;
            const float melt = fminf(fmaxf(CFMAX * (Tt - TT), 0.0f), SNOWPACK);
            MELTWATER += melt;
            SNOWPACK  -= melt;
            const float refreeze = fminf(fmaxf(CFRCFMAX * (TT - Tt), 0.0f), MELTWATER);
            SNOWPACK  += refreeze;
            MELTWATER -= refreeze;
            const float tosoil = fmaxf(MELTWATER - CWH * SNOWPACK, 0.0f);
            MELTWATER -= tosoil;

            // soil moisture
            const float ratio = SM * invFC;
            float sw = __powf(ratio, BETA);            // MUFU lg2 + ex2
            sw = fminf(fmaxf(sw, 0.0f), 1.0f);
            const float rt       = RAIN + tosoil;
            const float recharge = rt * sw;
            SM = SM + rt - recharge;
            const float excess = fmaxf(SM - FC, 0.0f);
            const float ef     = fminf(fmaxf(SM * invLPFC, 0.0f), 1.0f);
            const float ETact  = fminf(SM, PETt * ef);
            SM = fmaxf(SM - ETact, 1e-5f);

            // routing
            SUZ = SUZ + recharge + excess;
            const float PERC = fminf(SUZ, PERCmax);
            SUZ -= PERC;
            const float Q0 = K0 * fmaxf(SUZ - UZL, 0.0f);
            SUZ -= Q0;
            const float Q1 = K1 * SUZ;
            SUZ -= Q1;
            SLZ += PERC;
            const float Q2 = K2 * SLZ;
            SLZ -= Q2;
            const float Qsim = Q0 + Q1 + Q2;

            q_out[oidx] = Qsim;
            a_out[oidx] = ETact;
            s_out[oidx] = SNOWPACK;
            oidx += NGRID;
        }

        // rotate prefetch buffer
#pragma unroll
        for (int j = 0; j < PFD; ++j) {
            bP[j] = nP[j]; bT[j] = nT[j]; bE[j] = nE[j];
        }
    }
}

extern "C" void kernel_launch(void* const* d_in, const int* in_sizes, int n_in,
                              void* d_out, int out_size)
{
    const float* x      = (const float*)d_in[0];
    const float* params = (const float*)d_in[1];
    float* out          = (float*)d_out;

    const int threads = 128;
    const int blocks  = (NGRID + threads - 1) / threads;  // 79
    hbv_kernel<<<blocks, threads>>>(x, params, out);
}

// round 6
// speedup vs baseline: 1.1834x; 1.1834x over previous
#include <cuda_runtime.h>
#include <cstddef>

// HBV fused time-scan, software-pipelined stages.
// Snow recurrence runs ONE STEP AHEAD of the soil/routing recurrence so the
// per-step wall-clock chain is only the soil-moisture ladder (~56 cyc), not
// the serialized snow->soil->routing chain (~220 cyc, measured R1).

#define NSTEP 730
#define NGRID 10000
#define PFD   10
#define NEARZERO 1e-5f

__device__ __forceinline__ float fast_exp2(float v) {
    float r;
    asm("ex2.approx.ftz.f32 %0, %1;" : "=f"(r) : "f"(v));
    return r;   // MUFU.EX2
}

__global__ __launch_bounds__(128, 1)
void hbv_kernel(const float* __restrict__ x,
                const float* __restrict__ params,
                float* __restrict__ out)
{
    const int cell = blockIdx.x * blockDim.x + threadIdx.x;
    if (cell >= NGRID) return;

    const float* p = params + ((size_t)(NSTEP - 1) * NGRID + (size_t)cell) * 12;
    const float BETA    = 1.0f   + p[0]  * 5.0f;
    const float FC      = 50.0f  + p[1]  * 950.0f;
    const float K0      = 0.05f  + p[2]  * 0.85f;
    const float K1      = 0.01f  + p[3]  * 0.49f;
    const float K2      = 0.001f + p[4]  * 0.199f;
    const float LP      = 0.2f   + p[5]  * 0.8f;
    const float PERCmax =          p[6]  * 10.0f;
    const float UZL     =          p[7]  * 100.0f;
    const float TT      = -2.5f  + p[8]  * 5.0f;
    const float CFMAX   = 0.5f   + p[9]  * 9.5f;
    const float CFR     =          p[10] * 0.1f;
    const float CWH     =          p[11] * 0.2f;

    const float invLPFC   = 1.0f / (LP * FC);
    const float CFRCFMAX  = CFR * CFMAX;
    // sw = (SM/FC)^BETA = exp2(BETA*log2(SM) + BETA*log2(1/FC))
    const float betaLgInvFC = BETA * __log2f(1.0f / FC);

    float SNOWPACK = 0.001f, MELTWATER = 0.001f, SM = 0.001f;
    float SUZ = 0.001f, SLZ = 0.001f;

    const size_t n = (size_t)NSTEP * NGRID;
    float* __restrict__ q_out = out;
    float* __restrict__ a_out = out + n;
    float* __restrict__ s_out = out + 2 * n;

    // ---- input prefetch double buffers ----
    float bP[PFD], bT[PFD], bE[PFD];
    float nP[PFD], nT[PFD], nE[PFD];
#pragma unroll
    for (int j = 0; j < PFD; ++j) {
        const float* xp = x + ((size_t)j * NGRID + (size_t)cell) * 3;
        bP[j] = xp[0]; bT[j] = xp[1]; bE[j] = xp[2];
    }

    // staged values produced by snow stage (step t), consumed by soil stage (t)
    float rt_s, PET_s, c1_s;

    int sidx = cell;   // store index for SWE   (snow stage, step t)
    int midx = cell;   // store index for Q/AET (soil stage, step t-1)

#define SNOW_STAGE(Pt_, Tt_, Et_)                                            \
    {                                                                        \
        const float Pt = (Pt_), Tt = (Tt_), Et = (Et_);                      \
        const float RAIN = (Tt >= TT) ? Pt : 0.0f;                           \
        SNOWPACK += (Pt - RAIN);                                             \
        const float melt = fminf(fmaxf(CFMAX * (Tt - TT), 0.0f), SNOWPACK);  \
        MELTWATER += melt;                                                   \
        SNOWPACK  -= melt;                                                   \
        const float refr = fminf(fmaxf(CFRCFMAX * (TT - Tt), 0.0f), MELTWATER); \
        SNOWPACK  += refr;                                                   \
        MELTWATER -= refr;                                                   \
        const float tosoil = fmaxf(MELTWATER - CWH * SNOWPACK, 0.0f);        \
        MELTWATER -= tosoil;                                                 \
        rt_s  = RAIN + tosoil;                                               \
        PET_s = Et;                                                          \
        c1_s  = Et * invLPFC;                                                \
        s_out[sidx] = SNOWPACK;                                              \
        sidx += NGRID;                                                       \
    }

#define SOIL_STAGE()                                                         \
    {                                                                        \
        const float rt  = rt_s, PET = PET_s, c1 = c1_s;                      \
        const float lg  = __log2f(SM);                                       \
        float sw        = fast_exp2(fmaf(BETA, lg, betaLgInvFC));            \
        sw              = fminf(sw, 1.0f);                                   \
        const float a   = SM + rt;                                           \
        const float recharge = rt * sw;                                      \
        const float SMn = a - recharge;                                      \
        const float excess = fmaxf(SMn - FC, 0.0f);                          \
        const float ET  = fminf(fminf(SMn * c1, PET), SMn);                  \
        /* SM' = max(SMn - ET, eps) = max(SMn*(1-c1), SMn-PET, eps) */       \
        SM = fmaxf(fmaxf(fmaf(-c1, SMn, SMn), SMn - PET), NEARZERO);         \
        const float SUZa = SUZ + recharge + excess;                          \
        const float PERC = fminf(SUZa, PERCmax);                             \
        const float SUZb = SUZa - PERC;                                      \
        const float Q0   = K0 * fmaxf(SUZb - UZL, 0.0f);                     \
        const float SUZc = SUZb - Q0;                                        \
        const float Q1   = K1 * SUZc;                                        \
        SUZ = SUZc - Q1;                                                     \
        SLZ = SLZ + PERC;                                                    \
        const float Q2 = K2 * SLZ;                                           \
        SLZ = SLZ - Q2;                                                      \
        q_out[midx] = Q0 + Q1 + Q2;                                          \
        a_out[midx] = ET;                                                    \
        midx += NGRID;                                                       \
    }

#define PREFETCH_CHUNK(tb)                                                   \
    {                                                                        \
        _Pragma("unroll")                                                    \
        for (int j = 0; j < PFD; ++j) {                                      \
            const float* xp = x + ((size_t)((tb) + j) * NGRID + (size_t)cell) * 3; \
            nP[j] = xp[0]; nT[j] = xp[1]; nE[j] = xp[2];                     \
        }                                                                    \
    }

#define ROTATE_BUF()                                                         \
    {                                                                        \
        _Pragma("unroll")                                                    \
        for (int j = 0; j < PFD; ++j) { bP[j]=nP[j]; bT[j]=nT[j]; bE[j]=nE[j]; } \
    }

    // ---- chunk 0 (peeled: snow leads by one step) ----
    PREFETCH_CHUNK(PFD);            // chunk 1
    SNOW_STAGE(bP[0], bT[0], bE[0]);
#pragma unroll
    for (int j = 1; j < PFD; ++j) {
        SOIL_STAGE();               // step j-1
        SNOW_STAGE(bP[j], bT[j], bE[j]);  // step j
    }

    // ---- main chunks 1..71 (prefetch next) ----
    for (int c = 1; c < (NSTEP / PFD) - 1; ++c) {
        ROTATE_BUF();
        PREFETCH_CHUNK((c + 1) * PFD);
#pragma unroll
        for (int j = 0; j < PFD; ++j) {
            SOIL_STAGE();
            SNOW_STAGE(bP[j], bT[j], bE[j]);
        }
    }

    // ---- last chunk (72): no prefetch ----
    ROTATE_BUF();
#pragma unroll
    for (int j = 0; j < PFD; ++j) {
        SOIL_STAGE();
        SNOW_STAGE(bP[j], bT[j], bE[j]);
    }

    // ---- epilogue: soil stage for step 729 ----
    SOIL_STAGE();
}

extern "C" void kernel_launch(void* const* d_in, const int* in_sizes, int n_in,
                              void* d_out, int out_size)
{
    const float* x      = (const float*)d_in[0];
    const float* params = (const float*)d_in[1];
    float* out          = (float*)d_out;

    const int threads = 128;
    const int blocks  = (NGRID + threads - 1) / threads;  // 79
    hbv_kernel<<<blocks, threads>>>(x, params, out);
}

// round 10
// speedup vs baseline: 1.1977x; 1.0121x over previous
#include <cuda_runtime.h>
#include <cstddef>

// HBV fused time-scan, explicitly software-pipelined 3-stage schedule.
// Per step body, PROGRAM ORDER packs independent work into MUFU stall shadows:
//   LG2/FMA/EX2 for soil(t)  -> ROUTING(t-1)+stores -> SNOW(t+1)+store -> SOIL_TAIL(t)
// Snow leads by 1 step; routing trails by 1 step (staged in registers).

#define NSTEP 730
#define NGRID 10000
#define PFD   10
#define NEARZERO 1e-5f

__device__ __forceinline__ float fast_exp2(float v) {
    float r;
    asm("ex2.approx.ftz.f32 %0, %1;" : "=f"(r) : "f"(v));
    return r;   // MUFU.EX2
}

__global__ __launch_bounds__(128, 1)
void hbv_kernel(const float* __restrict__ x,
                const float* __restrict__ params,
                float* __restrict__ out)
{
    const int cell = blockIdx.x * blockDim.x + threadIdx.x;
    if (cell >= NGRID) return;

    const float* p = params + ((size_t)(NSTEP - 1) * NGRID + (size_t)cell) * 12;
    const float BETA    = 1.0f   + p[0]  * 5.0f;
    const float FC      = 50.0f  + p[1]  * 950.0f;
    const float K0      = 0.05f  + p[2]  * 0.85f;
    const float K1      = 0.01f  + p[3]  * 0.49f;
    const float K2      = 0.001f + p[4]  * 0.199f;
    const float LP      = 0.2f   + p[5]  * 0.8f;
    const float PERCmax =          p[6]  * 10.0f;
    const float UZL     =          p[7]  * 100.0f;
    const float TT      = -2.5f  + p[8]  * 5.0f;
    const float CFMAX   = 0.5f   + p[9]  * 9.5f;
    const float CFR     =          p[10] * 0.1f;
    const float CWH     =          p[11] * 0.2f;

    const float invLPFC     = 1.0f / (LP * FC);
    const float CFRCFMAX    = CFR * CFMAX;
    const float betaLgInvFC = BETA * __log2f(1.0f / FC);  // (SM/FC)^B = exp2(B*lg(SM)+this)

    float SNOWPACK = 0.001f, MELTWATER = 0.001f, SM = 0.001f;
    float SUZ = 0.001f, SLZ = 0.001f;

    const size_t n = (size_t)NSTEP * NGRID;
    float* __restrict__ q_out = out;
    float* __restrict__ a_out = out + n;
    float* __restrict__ s_out = out + 2 * n;

    // snow->soil staging (snow leads 1 step)
    float rt_c, c1_c, PET_c;      // consumed by soil(t)
    float rt_n, c1_n, PET_n;      // produced by snow(t+1)
    // soil->routing staging (routing trails 1 step)
    float rech_s = 0.0f, exc_s = 0.0f, ET_s = 0.0f;

    int sidx = cell;   // SWE store index (snow stage)
    int midx = cell;   // Q/AET store index (routing stage)

    // Buffers hold SNOW-stage inputs: chunk c covers steps c*PFD+1 .. c*PFD+PFD
    float bP[PFD], bT[PFD], bE[PFD];
    float nP[PFD], nT[PFD], nE[PFD];

#define ROUTING_EMIT()                                                       \
    {                                                                        \
        const float SUZa = SUZ + rech_s + exc_s;                             \
        const float PERC = fminf(SUZa, PERCmax);                             \
        const float SUZb = SUZa - PERC;                                      \
        const float Q0   = K0 * fmaxf(SUZb - UZL, 0.0f);                     \
        const float SUZc = SUZb - Q0;                                        \
        const float Q1   = K1 * SUZc;                                        \
        SUZ = SUZc - Q1;                                                     \
        SLZ = SLZ + PERC;                                                    \
        const float Q2 = K2 * SLZ;                                           \
        SLZ = SLZ - Q2;                                                      \
        q_out[midx] = Q0 + Q1 + Q2;                                          \
        a_out[midx] = ET_s;                                                  \
        midx += NGRID;                                                       \
    }

#define SNOW_EMIT(Pt_, Tt_, Et_)                                             \
    {                                                                        \
        const float Pt = (Pt_), Tt = (Tt_), Et = (Et_);                      \
        const float RAIN = (Tt >= TT) ? Pt : 0.0f;                           \
        SNOWPACK += (Pt - RAIN);                                             \
        const float melt = fminf(fmaxf(CFMAX * (Tt - TT), 0.0f), SNOWPACK);  \
        MELTWATER += melt;                                                   \
        SNOWPACK  -= melt;                                                   \
        const float refr = fminf(fmaxf(CFRCFMAX * (TT - Tt), 0.0f), MELTWATER); \
        SNOWPACK  += refr;                                                   \
        MELTWATER -= refr;                                                   \
        const float tosoil = fmaxf(MELTWATER - CWH * SNOWPACK, 0.0f);        \
        MELTWATER -= tosoil;                                                 \
        rt_n  = RAIN + tosoil;                                               \
        c1_n  = Et * invLPFC;                                                \
        PET_n = Et;                                                          \
        s_out[sidx] = SNOWPACK;                                              \
        sidx += NGRID;                                                       \
    }

#define NOOP {}

    // One full pipelined step. SNOWP/ROUTP are placed INSIDE the MUFU shadow.
#define STEP(SNOWP, ROUTP)                                                   \
    {                                                                        \
        const float lg = __log2f(SM);                                        \
        const float sw = fast_exp2(fmaf(BETA, lg, betaLgInvFC));             \
        ROUTP;                                                               \
        SNOWP;                                                               \
        const float a   = SM + rt_c;                                         \
        const float SMn = fmaxf(fmaf(-rt_c, sw, a), SM);  /* min(sw,1) folded */ \
        rech_s = a - SMn;                     /* == recharge exactly */      \
        exc_s  = fmaxf(SMn - FC, 0.0f);                                      \
        ET_s   = fminf(fminf(SMn * c1_c, PET_c), SMn);                       \
        SM = fmaxf(fmaxf(fmaf(-c1_c, SMn, SMn), SMn - PET_c), NEARZERO);     \
        rt_c = rt_n; c1_c = c1_n; PET_c = PET_n;                             \
    }

    // loads snow inputs for steps base+1+j (clamped to last valid step)
#define PREFETCH_CHUNK(base)                                                 \
    {                                                                        \
        _Pragma("unroll")                                                    \
        for (int j = 0; j < PFD; ++j) {                                      \
            int st = (base) + 1 + j;                                         \
            if (st > NSTEP - 1) st = NSTEP - 1;                              \
            const float* xp = x + ((size_t)st * NGRID + (size_t)cell) * 3;   \
            nP[j] = xp[0]; nT[j] = xp[1]; nE[j] = xp[2];                     \
        }                                                                    \
    }

#define ROTATE_BUF()                                                         \
    {                                                                        \
        _Pragma("unroll")                                                    \
        for (int j = 0; j < PFD; ++j) { bP[j]=nP[j]; bT[j]=nT[j]; bE[j]=nE[j]; } \
    }

    // ---- prologue ----
    // step-0 inputs
    const float* x0 = x + (size_t)cell * 3;
    const float P0 = x0[0], T0 = x0[1], E0 = x0[2];
    // buffer chunk 0: snow inputs steps 1..10 ; prefetch chunk 1: steps 11..20
    {
#pragma unroll
        for (int j = 0; j < PFD; ++j) {
            const float* xp = x + ((size_t)(1 + j) * NGRID + (size_t)cell) * 3;
            bP[j] = xp[0]; bT[j] = xp[1]; bE[j] = xp[2];
        }
    }
    PREFETCH_CHUNK(PFD);

    // snow(0) -> staging for soil(0)
    SNOW_EMIT(P0, T0, E0);
    rt_c = rt_n; c1_c = c1_n; PET_c = PET_n;

    // ---- chunk 0: body(0) has no routing ----
    STEP(SNOW_EMIT(bP[0], bT[0], bE[0]), NOOP);
#pragma unroll
    for (int j = 1; j < PFD; ++j)
        STEP(SNOW_EMIT(bP[j], bT[j], bE[j]), ROUTING_EMIT());

    // ---- chunks 1..71: steady state with prefetch of chunk c+1 ----
    for (int c = 1; c < (NSTEP / PFD) - 1; ++c) {
        ROTATE_BUF();
        PREFETCH_CHUNK((c + 1) * PFD);
#pragma unroll
        for (int j = 0; j < PFD; ++j)
            STEP(SNOW_EMIT(bP[j], bT[j], bE[j]), ROUTING_EMIT());
    }

    // ---- chunk 72: bodies 720..728 full, body 729 without snow ----
    ROTATE_BUF();
#pragma unroll
    for (int j = 0; j < PFD - 1; ++j)
        STEP(SNOW_EMIT(bP[j], bT[j], bE[j]), ROUTING_EMIT());
    STEP(NOOP, ROUTING_EMIT());

    // ---- epilogue: routing for step 729 ----
    ROUTING_EMIT();
}

extern "C" void kernel_launch(void* const* d_in, const int* in_sizes, int n_in,
                              void* d_out, int out_size)
{
    const float* x      = (const float*)d_in[0];
    const float* params = (const float*)d_in[1];
    float* out          = (float*)d_out;

    const int threads = 128;
    const int blocks  = (NGRID + threads - 1) / threads;  // 79
    hbv_kernel<<<blocks, threads>>>(x, params, out);
}